// round 1
// baseline (speedup 1.0000x reference)
#include <cuda_runtime.h>

#define NB   512
#define NC   480
#define NP   15
#define NHW  225                  // 15*15
#define SLICE (NC * NHW)          // 108000 floats per batch
#define NTHREADS 1024
#define DYN_SMEM (120 * 1024)     // force 1 CTA/SM -> per-wave L2 working set 64MB < 126MB

__global__ __launch_bounds__(NTHREADS, 1)
void ncam3d_kernel(const float* __restrict__ x,
                   const float* __restrict__ w1, const float* __restrict__ b1,
                   const float* __restrict__ w2, const float* __restrict__ b2,
                   float* __restrict__ out)
{
    extern __shared__ float smem[];
    float* s_full = smem;            // [480] full-slice means
    float* s_cent = smem + NC;       // [480] masked (center 3x3) means
    float* s_at   = smem + 2 * NC;   // [481] gate per channel (+1 pad for vec crossing)

    const int b   = blockIdx.x;
    const float* __restrict__ xb = x + (size_t)b * SLICE;
    float* __restrict__       ob = out + (size_t)b * SLICE;
    const int tid  = threadIdx.x;
    const int warp = tid >> 5;
    const int lane = tid & 31;

    // ---------------- Phase 1: per-channel reductions (warp per channel) ----
    for (int c = warp; c < NC; c += (NTHREADS / 32)) {
        const float* row = xb + c * NHW;
        float sf = 0.f, sc = 0.f;
        for (int i = lane; i < NHW; i += 32) {
            float v = __ldg(row + i);
            sf += v;
            int h = i / NP;
            int w = i - h * NP;
            // ring mask with d=6 on n=15 => center 3x3 block (h,w in [6,8])
            if ((unsigned)(h - 6) < 3u && (unsigned)(w - 6) < 3u) sc += v;
        }
        #pragma unroll
        for (int off = 16; off; off >>= 1) {
            sf += __shfl_xor_sync(0xffffffffu, sf, off);
            sc += __shfl_xor_sync(0xffffffffu, sc, off);
        }
        if (lane == 0) {
            s_full[c] = sf * (1.0f / 225.0f);
            s_cent[c] = sc * (1.0f / 225.0f);
        }
    }
    __syncthreads();

    // ---------------- Phase 2: gate per channel (conv 2x5 over channel axis) -
    if (tid < NC) {
        const int c = tid;
        float acc1 = __ldg(b1);
        float acc2 = __ldg(b2);
        #pragma unroll
        for (int k = 0; k < 5; k++) {
            int j = c + k - 2;
            if ((unsigned)j < (unsigned)NC) {
                // conv row 0 = means, row 1 = channel-reversed means
                acc1 = fmaf(__ldg(w1 + k),     s_full[j],          acc1);
                acc1 = fmaf(__ldg(w1 + 5 + k), s_full[NC - 1 - j], acc1);
                acc2 = fmaf(__ldg(w2 + k),     s_cent[j],          acc2);
                acc2 = fmaf(__ldg(w2 + 5 + k), s_cent[NC - 1 - j], acc2);
            }
        }
        float a1 = 1.0f / (1.0f + __expf(-acc1));
        float a2 = 1.0f / (1.0f + __expf(-acc2));
        float p  = (a1 * a2 - 0.2f) * 2.0f;
        s_at[c]  = 1.0f / (1.0f + __expf(-p));
    } else if (tid == NC) {
        s_at[NC] = 0.f;  // pad so vec4 channel-crossing reads are in-bounds
    }
    __syncthreads();

    // ---------------- Phase 3: scale + write (vectorized streaming) ---------
    const float4* __restrict__ xv = (const float4*)xb;
    float4* __restrict__       ov = (float4*)ob;
    for (int i = tid; i < SLICE / 4; i += NTHREADS) {
        float4 v = xv[i];
        int e  = i * 4;
        int c0 = e / NHW;            // constant division -> mul/shift
        int r  = e - c0 * NHW;
        float a0 = s_at[c0];
        float an = s_at[c0 + 1];     // padded; only used when crossing
        v.x *= a0;
        v.y *= (r + 1 < NHW) ? a0 : an;
        v.z *= (r + 2 < NHW) ? a0 : an;
        v.w *= (r + 3 < NHW) ? a0 : an;
        ov[i] = v;
    }
}

extern "C" void kernel_launch(void* const* d_in, const int* in_sizes, int n_in,
                              void* d_out, int out_size)
{
    const float* x  = (const float*)d_in[0];
    const float* w1 = (const float*)d_in[1];
    const float* b1 = (const float*)d_in[2];
    const float* w2 = (const float*)d_in[3];
    const float* b2 = (const float*)d_in[4];
    float* out = (float*)d_out;

    cudaFuncSetAttribute(ncam3d_kernel,
                         cudaFuncAttributeMaxDynamicSharedMemorySize, DYN_SMEM);
    ncam3d_kernel<<<NB, NTHREADS, DYN_SMEM>>>(x, w1, b1, w2, b2, out);
}